// round 10
// baseline (speedup 1.0000x reference)
#include <cuda_runtime.h>
#include <cuda_fp16.h>

#define N_NODES 50000
#define N_EDGES 800000
#define HID 128
#define N_GRAPHS 64
#define CAP 64          // padded CSR bucket capacity (P(deg>=64) ~ 1e-18)

// ---------------- scratch (static device globals; no allocation) ----------
__device__ float  g_bufA[N_NODES * HID];       // aggregated h1 (fp32)
__device__ float  g_bufB[N_NODES * HID];       // h2 (fp32)
__device__ __half g_hs[(N_NODES + 1) * HID];   // dinv_i*h1_i (fp16) + zero row
__device__ float  g_xs[(N_NODES + 1) * 16];    // dinv_i*x_i + zero row
__device__ int    g_cur[N_NODES];              // in-degree (atomic bump)
__device__ int    g_csr[N_NODES * CAP];        // padded buckets of source ids
__device__ float  g_dinv[N_NODES];
__device__ float  g_pool[N_GRAPHS * HID];
__device__ int    g_gcnt[N_GRAPHS];
__device__ int    g_is64;

// ---------------- helpers ---------------------------------------------------
__device__ __forceinline__ int ld_idx(const void* p, long long i, int is64) {
    if (is64) return (int)((const long long*)p)[i];
    return ((const int*)p)[i];
}

__device__ __forceinline__ void fma2(unsigned long long& d,
                                     unsigned long long a,
                                     unsigned long long b) {
    asm("fma.rn.f32x2 %0, %1, %2, %3;" : "=l"(d) : "l"(a), "l"(b), "l"(d));
}
__device__ __forceinline__ unsigned long long pack2(float x, float y) {
    unsigned long long r;
    asm("mov.b64 %0, {%1, %2};" : "=l"(r) : "f"(x), "f"(y));
    return r;
}
__device__ __forceinline__ void unpack2(unsigned long long v, float& x, float& y) {
    asm("mov.b64 {%0, %1}, %2;" : "=f"(x), "=f"(y) : "l"(v));
}

__device__ __forceinline__ float4 h4_to_f4(unsigned int a, unsigned int b) {
    float2 p = __half22float2(*(const __half2*)&a);
    float2 q = __half22float2(*(const __half2*)&b);
    return make_float4(p.x, p.y, q.x, q.y);
}

// local int64/int32 detection from the first 64 index values (deterministic)
__device__ __forceinline__ int detect64(const void* ei, int tid, int* s_flag) {
    if (tid == 0) *s_flag = 1;
    __syncthreads();
    if (tid < 64) {
        long long v = ((const long long*)ei)[tid];
        if (v < 0 || v >= N_NODES) *s_flag = 0;
    }
    __syncthreads();
    return *s_flag;
}

// ---------------- kernels ---------------------------------------------------
__global__ void k_init() {
    int i = blockIdx.x * blockDim.x + threadIdx.x;
    if (i < N_NODES) g_cur[i] = 0;
    if (i < N_GRAPHS * HID) g_pool[i] = 0.f;
    if (i < N_GRAPHS) g_gcnt[i] = 0;
    if (i < 16) g_xs[N_NODES * 16 + i] = 0.f;           // zero sentinel row
    if (i < HID) g_hs[N_NODES * HID + i] = __float2half(0.f);
}

// single-pass padded-bucket CSR build
__global__ void k_build(const void* ei) {
    __shared__ int s_is64;
    int tid = threadIdx.x;
    int is64 = detect64(ei, tid, &s_is64);
    int e = blockIdx.x * blockDim.x + tid;
    if (e < N_EDGES) {
        int s = ld_idx(ei, e, is64);
        int d = ld_idx(ei, (long long)N_EDGES + e, is64);
        int slot = atomicAdd(&g_cur[d], 1);
        if (slot < CAP) g_csr[d * CAP + slot] = s;
    }
    if (blockIdx.x == 0 && tid == 0) g_is64 = is64;
}

// dinv + pre-scaled features xs = dinv_i * x_i
__global__ void k_dinvxs(const float* __restrict__ x) {
    int t = blockIdx.x * blockDim.x + threadIdx.x;
    int i = t >> 4;                 // node
    int col = t & 15;
    if (i >= N_NODES) return;
    float di = rsqrtf((float)(g_cur[i] + 1));   // +1 self-loop
    if (col == 0) g_dinv[i] = di;
    g_xs[i * 16 + col] = x[i * 16 + col] * di;
}

// Fused layer 1, W1 register-resident, grid-stride warps.
// Per node: gather (8 edges per LDG.128 round) + shfl reduce + pure-FFMA GEMM.
// Zero per-node LDS traffic — W1 slice (16 float4) lives in registers.
__global__ void __launch_bounds__(256) k_l1(const float* __restrict__ W1,
                                            const float* __restrict__ b1) {
    __shared__ float W1s[16 * 128];
    int tid = threadIdx.x;
    {   // stage W1 (coalesced), then pull this lane's slice into registers
        float4* d4 = (float4*)W1s;
        const float4* s4 = (const float4*)W1;
        d4[tid] = s4[tid];
        d4[tid + 256] = s4[tid + 256];
    }
    __syncthreads();
    int lane = tid & 31;
    const float4* W1s4 = (const float4*)W1s;
    float4 w1r[16];
    #pragma unroll
    for (int k = 0; k < 16; k++) w1r[k] = W1s4[k * 32 + lane];
    float4 bias = ((const float4*)b1)[lane];

    int grp = lane >> 2;    // 0..7 edge group
    int sub = lane & 3;     // float4 slot within 16-float row
    const float4* xs4 = (const float4*)g_xs;

    int gwarp = (blockIdx.x * blockDim.x + tid) >> 5;
    int nwarp = (gridDim.x * blockDim.x) >> 5;
    for (int i = gwarp; i < N_NODES; i += nwarp) {
        float di = g_dinv[i];
        float4 acc = (grp == 0) ? xs4[i * 4 + sub]
                                : make_float4(0.f, 0.f, 0.f, 0.f);  // self
        int base = i * CAP;
        int deg = min(g_cur[i], CAP);
        for (int e = 0; e < deg; e += 8) {
            int idx = e + grp;
            int s = (idx < deg) ? g_csr[base + idx] : N_NODES;  // sentinel->0
            float4 v = xs4[s * 4 + sub];
            acc.x += v.x; acc.y += v.y; acc.z += v.z; acc.w += v.w;
        }
        // reduce over the 8 groups
        #pragma unroll
        for (int off = 4; off < 32; off <<= 1) {
            acc.x += __shfl_xor_sync(0xffffffffu, acc.x, off);
            acc.y += __shfl_xor_sync(0xffffffffu, acc.y, off);
            acc.z += __shfl_xor_sync(0xffffffffu, acc.z, off);
            acc.w += __shfl_xor_sync(0xffffffffu, acc.w, off);
        }
        acc.x *= di; acc.y *= di; acc.z *= di; acc.w *= di;

        // h1 cols [4*lane..): lane (k>>2) holds xa[k] in component (k&3)
        float4 o = make_float4(0.f, 0.f, 0.f, 0.f);
        #pragma unroll
        for (int k = 0; k < 16; k++) {
            float comp = (k & 3) == 0 ? acc.x : (k & 3) == 1 ? acc.y
                       : (k & 3) == 2 ? acc.z : acc.w;
            float xk = __shfl_sync(0xffffffffu, comp, k >> 2);
            o.x = fmaf(xk, w1r[k].x, o.x);
            o.y = fmaf(xk, w1r[k].y, o.y);
            o.z = fmaf(xk, w1r[k].z, o.z);
            o.w = fmaf(xk, w1r[k].w, o.w);
        }
        o.x = fmaxf(o.x + bias.x, 0.f) * di;    // hs = dinv_i * relu(h1)
        o.y = fmaxf(o.y + bias.y, 0.f) * di;
        o.z = fmaxf(o.z + bias.z, 0.f) * di;
        o.w = fmaxf(o.w + bias.w, 0.f) * di;
        __half2 lo = __floats2half2_rn(o.x, o.y);
        __half2 hi = __floats2half2_rn(o.z, o.w);
        uint2 pk;
        pk.x = *(const unsigned int*)&lo;
        pk.y = *(const unsigned int*)&hi;
        ((uint2*)g_hs)[i * 32 + lane] = pk;
    }
}

// Aggregate hs (fp16): bufA_i = di * (hs[i] + sum_e hs[s]).
// One warp per node; 2 edge-groups of 16 lanes, uint4 (8 halves) per lane.
__global__ void k_aggh() {
    int i = (blockIdx.x * blockDim.x + threadIdx.x) >> 5;
    if (i >= N_NODES) return;
    int lane = threadIdx.x & 31;
    int grp = lane >> 4;    // 0..1
    int sub = lane & 15;    // uint4 slot within 128-half row
    float di = g_dinv[i];
    const uint4* __restrict__ h = (const uint4*)g_hs;

    float4 a0, a1;
    if (grp == 0) {         // self term
        uint4 sv = h[i * 16 + sub];
        a0 = h4_to_f4(sv.x, sv.y);
        a1 = h4_to_f4(sv.z, sv.w);
    } else {
        a0 = make_float4(0.f, 0.f, 0.f, 0.f);
        a1 = make_float4(0.f, 0.f, 0.f, 0.f);
    }

    int base = i * CAP;
    int deg = min(g_cur[i], CAP);
    for (int e = 0; e < deg; e += 4) {
        int i0 = e + grp;
        int i1 = e + grp + 2;
        int s0 = (i0 < deg) ? g_csr[base + i0] : N_NODES;
        int s1 = (i1 < deg) ? g_csr[base + i1] : N_NODES;
        uint4 v0 = h[s0 * 16 + sub];
        uint4 v1 = h[s1 * 16 + sub];
        float4 f00 = h4_to_f4(v0.x, v0.y);
        float4 f01 = h4_to_f4(v0.z, v0.w);
        float4 f10 = h4_to_f4(v1.x, v1.y);
        float4 f11 = h4_to_f4(v1.z, v1.w);
        a0.x += f00.x + f10.x; a0.y += f00.y + f10.y;
        a0.z += f00.z + f10.z; a0.w += f00.w + f10.w;
        a1.x += f01.x + f11.x; a1.y += f01.y + f11.y;
        a1.z += f01.z + f11.z; a1.w += f01.w + f11.w;
    }
    // combine the 2 groups
    a0.x += __shfl_xor_sync(0xffffffffu, a0.x, 16);
    a0.y += __shfl_xor_sync(0xffffffffu, a0.y, 16);
    a0.z += __shfl_xor_sync(0xffffffffu, a0.z, 16);
    a0.w += __shfl_xor_sync(0xffffffffu, a0.w, 16);
    a1.x += __shfl_xor_sync(0xffffffffu, a1.x, 16);
    a1.y += __shfl_xor_sync(0xffffffffu, a1.y, 16);
    a1.z += __shfl_xor_sync(0xffffffffu, a1.z, 16);
    a1.w += __shfl_xor_sync(0xffffffffu, a1.w, 16);

    a0.x *= di; a0.y *= di; a0.z *= di; a0.w *= di;
    a1.x *= di; a1.y *= di; a1.z *= di; a1.w *= di;
    float4* out4 = (float4*)g_bufA;
    out4[i * 32 + 2 * sub + grp] = (grp == 0) ? a0 : a1;
}

// h2 = relu(bufA @ W2 + b2) -> bufB.  BM=64, BN=128, BK=16, 256 threads.
// Inner loop in packed fp32x2.
__global__ void k_gemm2(const float* __restrict__ W2, const float* __restrict__ b2) {
    __shared__ float As[16][64];
    __shared__ float Bs[16][128];
    int tid = threadIdx.x;
    int tx = tid & 31;
    int ty = tid >> 5;
    int row0 = blockIdx.x * 64;
    unsigned long long acc2[4][4];
    #pragma unroll
    for (int q = 0; q < 4; q++)
        #pragma unroll
        for (int c = 0; c < 4; c++) acc2[q][c] = 0ull;

    const float* A = g_bufA;
    for (int k0 = 0; k0 < 128; k0 += 16) {
        {
            int r = tid >> 2;
            int kq = (tid & 3) * 4;
            int row = row0 + r;
            float4 v = make_float4(0.f, 0.f, 0.f, 0.f);
            if (row < N_NODES)
                v = ((const float4*)A)[(row * 128 + k0 + kq) >> 2];
            As[kq + 0][r] = v.x;
            As[kq + 1][r] = v.y;
            As[kq + 2][r] = v.z;
            As[kq + 3][r] = v.w;
        }
        {
            const float4* W4 = (const float4*)(W2 + k0 * 128);
            float4* Bs4 = (float4*)&Bs[0][0];
            Bs4[tid] = W4[tid];
            Bs4[tid + 256] = W4[tid + 256];
        }
        __syncthreads();
        #pragma unroll
        for (int k = 0; k < 16; k++) {
            float4 b = *((float4*)&Bs[k][tx * 4]);
            unsigned long long bb[4];
            bb[0] = pack2(b.x, b.x);
            bb[1] = pack2(b.y, b.y);
            bb[2] = pack2(b.z, b.z);
            bb[3] = pack2(b.w, b.w);
            #pragma unroll
            for (int q = 0; q < 4; q++) {
                unsigned long long a2 =
                    *(const unsigned long long*)&As[k][ty * 8 + 2 * q];
                fma2(acc2[q][0], a2, bb[0]);
                fma2(acc2[q][1], a2, bb[1]);
                fma2(acc2[q][2], a2, bb[2]);
                fma2(acc2[q][3], a2, bb[3]);
            }
        }
        __syncthreads();
    }
    float4 bias = ((const float4*)b2)[tx];
    #pragma unroll
    for (int q = 0; q < 4; q++) {
        float lo[4], hi[4];
        #pragma unroll
        for (int c = 0; c < 4; c++) unpack2(acc2[q][c], lo[c], hi[c]);
        int r0 = row0 + ty * 8 + 2 * q;
        if (r0 < N_NODES) {
            float4 v = make_float4(fmaxf(lo[0] + bias.x, 0.f),
                                   fmaxf(lo[1] + bias.y, 0.f),
                                   fmaxf(lo[2] + bias.z, 0.f),
                                   fmaxf(lo[3] + bias.w, 0.f));
            ((float4*)g_bufB)[r0 * 32 + tx] = v;
        }
        if (r0 + 1 < N_NODES) {
            float4 v = make_float4(fmaxf(hi[0] + bias.x, 0.f),
                                   fmaxf(hi[1] + bias.y, 0.f),
                                   fmaxf(hi[2] + bias.z, 0.f),
                                   fmaxf(hi[3] + bias.w, 0.f));
            ((float4*)g_bufB)[(r0 + 1) * 32 + tx] = v;
        }
    }
}

// pool sums from bufB (batch sorted -> local accumulation); also graph counts.
__global__ void k_pool(const void* batch) {
    int tid = threadIdx.x;
    int start = blockIdx.x * 128;
    int end = min(start + 128, N_NODES);
    if (start >= N_NODES) return;
    int is64 = g_is64;
    int curg = ld_idx(batch, start, is64);
    float acc = 0.f;
    int runlen = 0;
    for (int n = start; n < end; n++) {
        int g = ld_idx(batch, n, is64);
        if (g != curg) {
            atomicAdd(&g_pool[curg * 128 + tid], acc);
            if (tid == 0) atomicAdd(&g_gcnt[curg], runlen);
            acc = 0.f; runlen = 0;
            curg = g;
        }
        acc += g_bufB[n * 128 + tid];
        runlen++;
    }
    atomicAdd(&g_pool[curg * 128 + tid], acc);
    if (tid == 0) atomicAdd(&g_gcnt[curg], runlen);
}

__global__ void k_final(const float* __restrict__ Wfc,
                        const float* __restrict__ bfc,
                        float* __restrict__ out) {
    int tid = threadIdx.x;   // 1024 = 64*16
    int g = tid >> 4;
    int o = tid & 15;
    float c = (float)max(g_gcnt[g], 1);
    float s = 0.f;
    #pragma unroll 8
    for (int k = 0; k < 128; k++)
        s = fmaf(g_pool[g * 128 + k], Wfc[k * 16 + o], s);
    out[tid] = s / c + bfc[o];
}

// ---------------- launch ----------------------------------------------------
extern "C" void kernel_launch(void* const* d_in, const int* in_sizes, int n_in,
                              void* d_out, int out_size) {
    const float* x   = (const float*)d_in[0];
    const void*  ei  = d_in[1];
    const void*  bat = d_in[2];
    const float* W1  = (const float*)d_in[3];
    const float* b1  = (const float*)d_in[4];
    const float* W2  = (const float*)d_in[5];
    const float* b2  = (const float*)d_in[6];
    const float* Wfc = (const float*)d_in[7];
    const float* bfc = (const float*)d_in[8];
    float* out = (float*)d_out;

    k_init<<<(N_NODES + 255) / 256, 256>>>();                 // 1
    k_build<<<(N_EDGES + 255) / 256, 256>>>(ei);              // 2
    k_dinvxs<<<(N_NODES * 16 + 255) / 256, 256>>>(x);         // 3
    k_l1<<<592, 256>>>(W1, b1);                               // 4  <- ncu slot
    k_aggh<<<(N_NODES + 7) / 8, 256>>>();                     // 5
    k_gemm2<<<(N_NODES + 63) / 64, 256>>>(W2, b2);            // 6
    k_pool<<<(N_NODES + 127) / 128, 128>>>(bat);              // 7
    k_final<<<1, 1024>>>(Wfc, bfc, out);                      // 8
}

// round 11
// speedup vs baseline: 1.0881x; 1.0881x over previous
#include <cuda_runtime.h>
#include <cuda_fp16.h>

#define N_NODES 50000
#define N_EDGES 800000
#define HID 128
#define N_GRAPHS 64
#define CAP 64          // padded CSR bucket capacity (P(deg>=64) ~ 1e-18)

// ---------------- scratch (static device globals; no allocation) ----------
__device__ float  g_bufA[N_NODES * HID];       // aggregated h1 (fp32)
__device__ float  g_bufB[N_NODES * HID];       // h2 (fp32)
__device__ __half g_hs[(N_NODES + 1) * HID];   // dinv_i*h1_i (fp16) + zero row
__device__ float  g_xs[(N_NODES + 1) * 16];    // dinv_i*x_i + zero row
__device__ float  g_xa[N_NODES * 16];          // aggregated, di-scaled x
__device__ int    g_cur[N_NODES];              // in-degree (atomic bump)
__device__ int    g_csr[N_NODES * CAP];        // padded buckets of source ids
__device__ float  g_dinv[N_NODES];
__device__ float  g_pool[N_GRAPHS * HID];
__device__ int    g_gcnt[N_GRAPHS];
__device__ int    g_is64;

// ---------------- helpers ---------------------------------------------------
__device__ __forceinline__ int ld_idx(const void* p, long long i, int is64) {
    if (is64) return (int)((const long long*)p)[i];
    return ((const int*)p)[i];
}

__device__ __forceinline__ void fma2(unsigned long long& d,
                                     unsigned long long a,
                                     unsigned long long b) {
    asm("fma.rn.f32x2 %0, %1, %2, %3;" : "=l"(d) : "l"(a), "l"(b), "l"(d));
}
__device__ __forceinline__ unsigned long long pack2(float x, float y) {
    unsigned long long r;
    asm("mov.b64 %0, {%1, %2};" : "=l"(r) : "f"(x), "f"(y));
    return r;
}
__device__ __forceinline__ void unpack2(unsigned long long v, float& x, float& y) {
    asm("mov.b64 {%0, %1}, %2;" : "=f"(x), "=f"(y) : "l"(v));
}

__device__ __forceinline__ float4 h4_to_f4(unsigned int a, unsigned int b) {
    float2 p = __half22float2(*(const __half2*)&a);
    float2 q = __half22float2(*(const __half2*)&b);
    return make_float4(p.x, p.y, q.x, q.y);
}

// local int64/int32 detection from the first 64 index values (deterministic)
__device__ __forceinline__ int detect64(const void* ei, int tid, int* s_flag) {
    if (tid == 0) *s_flag = 1;
    __syncthreads();
    if (tid < 64) {
        long long v = ((const long long*)ei)[tid];
        if (v < 0 || v >= N_NODES) *s_flag = 0;
    }
    __syncthreads();
    return *s_flag;
}

// ---------------- kernels ---------------------------------------------------
__global__ void k_init() {
    int i = blockIdx.x * blockDim.x + threadIdx.x;
    if (i < N_NODES) g_cur[i] = 0;
    if (i < N_GRAPHS * HID) g_pool[i] = 0.f;
    if (i < N_GRAPHS) g_gcnt[i] = 0;
    if (i < 16) g_xs[N_NODES * 16 + i] = 0.f;           // zero sentinel row
    if (i < HID) g_hs[N_NODES * HID + i] = __float2half(0.f);
}

// single-pass padded-bucket CSR build
__global__ void k_build(const void* ei) {
    __shared__ int s_is64;
    int tid = threadIdx.x;
    int is64 = detect64(ei, tid, &s_is64);
    int e = blockIdx.x * blockDim.x + tid;
    if (e < N_EDGES) {
        int s = ld_idx(ei, e, is64);
        int d = ld_idx(ei, (long long)N_EDGES + e, is64);
        int slot = atomicAdd(&g_cur[d], 1);
        if (slot < CAP) g_csr[d * CAP + slot] = s;
    }
    if (blockIdx.x == 0 && tid == 0) g_is64 = is64;
}

// dinv + pre-scaled features xs = dinv_i * x_i
__global__ void k_dinvxs(const float* __restrict__ x) {
    int t = blockIdx.x * blockDim.x + threadIdx.x;
    int i = t >> 4;                 // node
    int col = t & 15;
    if (i >= N_NODES) return;
    float di = rsqrtf((float)(g_cur[i] + 1));   // +1 self-loop
    if (col == 0) g_dinv[i] = di;
    g_xs[i * 16 + col] = x[i * 16 + col] * di;
}

// Pure gather for layer 1: xa_i = di*(xs[i] + sum_e xs[s]).
// One warp per node; 8 edge-groups of 4 lanes, float4 per lane
// (one LDG.128 round covers 8 edges). ~32 regs, high occupancy.
__global__ void k_aggx() {
    int i = (blockIdx.x * blockDim.x + threadIdx.x) >> 5;
    if (i >= N_NODES) return;
    int lane = threadIdx.x & 31;
    int grp = lane >> 2;    // 0..7 edge group
    int sub = lane & 3;     // float4 slot within 16-float row
    float di = g_dinv[i];
    const float4* xs4 = (const float4*)g_xs;

    float4 acc = (grp == 0) ? xs4[i * 4 + sub]
                            : make_float4(0.f, 0.f, 0.f, 0.f);   // self term
    int base = i * CAP;
    int deg = min(g_cur[i], CAP);
    for (int e = 0; e < deg; e += 8) {
        int idx = e + grp;
        int s = (idx < deg) ? g_csr[base + idx] : N_NODES;   // sentinel -> 0
        float4 v = xs4[s * 4 + sub];
        acc.x += v.x; acc.y += v.y; acc.z += v.z; acc.w += v.w;
    }
    #pragma unroll
    for (int off = 4; off < 32; off <<= 1) {
        acc.x += __shfl_xor_sync(0xffffffffu, acc.x, off);
        acc.y += __shfl_xor_sync(0xffffffffu, acc.y, off);
        acc.z += __shfl_xor_sync(0xffffffffu, acc.z, off);
        acc.w += __shfl_xor_sync(0xffffffffu, acc.w, off);
    }
    if (grp == 0) {
        acc.x *= di; acc.y *= di; acc.z *= di; acc.w *= di;
        ((float4*)g_xa)[i * 4 + sub] = acc;
    }
}

// Tiled layer-1 GEMM: hs = di * relu(xa @ W1 + b1), fp16 out.
// 32 rows/block, 128 threads (one output col each). W1 slice loaded ONCE
// per 32 nodes -> W1 shared-read traffic amortized 32x.
__global__ void __launch_bounds__(128) k_gemm1(const float* __restrict__ W1,
                                               const float* __restrict__ b1) {
    __shared__ float W1s[16 * 128];
    __shared__ float xas[32 * 16];
    __shared__ float dis[32];
    int tid = threadIdx.x;
    int row0 = blockIdx.x * 32;
    {   // W1: 2048 floats = 512 float4 / 128 threads
        float4* d4 = (float4*)W1s;
        const float4* s4 = (const float4*)W1;
        #pragma unroll
        for (int j = 0; j < 4; j++) d4[tid + 128 * j] = s4[tid + 128 * j];
    }
    {   // xa tile: 32 rows x 16 = 128 float4
        float4* d4 = (float4*)xas;
        const float4* s4 = (const float4*)g_xa;
        int r = row0 * 4 + tid;
        d4[tid] = (r < N_NODES * 4) ? s4[r] : make_float4(0.f, 0.f, 0.f, 0.f);
    }
    if (tid < 32) {
        int r = row0 + tid;
        dis[tid] = (r < N_NODES) ? g_dinv[r] : 0.f;
    }
    __syncthreads();

    float w[16];
    #pragma unroll
    for (int k = 0; k < 16; k++) w[k] = W1s[k * 128 + tid];
    float bias = b1[tid];
    int rmax = min(32, N_NODES - row0);
    for (int r = 0; r < rmax; r++) {
        float acc = bias;
        #pragma unroll
        for (int k = 0; k < 16; k++) acc = fmaf(xas[r * 16 + k], w[k], acc);
        float hsv = fmaxf(acc, 0.f) * dis[r];       // hs = di * relu(h1)
        g_hs[(row0 + r) * 128 + tid] = __float2half(hsv);
    }
}

// Aggregate hs (fp16): bufA_i = di * (hs[i] + sum_e hs[s]).
// One warp per node; 2 edge-groups of 16 lanes, uint4 (8 halves) per lane.
__global__ void k_aggh() {
    int i = (blockIdx.x * blockDim.x + threadIdx.x) >> 5;
    if (i >= N_NODES) return;
    int lane = threadIdx.x & 31;
    int grp = lane >> 4;    // 0..1
    int sub = lane & 15;    // uint4 slot within 128-half row
    float di = g_dinv[i];
    const uint4* __restrict__ h = (const uint4*)g_hs;

    float4 a0, a1;
    if (grp == 0) {         // self term
        uint4 sv = h[i * 16 + sub];
        a0 = h4_to_f4(sv.x, sv.y);
        a1 = h4_to_f4(sv.z, sv.w);
    } else {
        a0 = make_float4(0.f, 0.f, 0.f, 0.f);
        a1 = make_float4(0.f, 0.f, 0.f, 0.f);
    }

    int base = i * CAP;
    int deg = min(g_cur[i], CAP);
    for (int e = 0; e < deg; e += 4) {
        int i0 = e + grp;
        int i1 = e + grp + 2;
        int s0 = (i0 < deg) ? g_csr[base + i0] : N_NODES;
        int s1 = (i1 < deg) ? g_csr[base + i1] : N_NODES;
        uint4 v0 = h[s0 * 16 + sub];
        uint4 v1 = h[s1 * 16 + sub];
        float4 f00 = h4_to_f4(v0.x, v0.y);
        float4 f01 = h4_to_f4(v0.z, v0.w);
        float4 f10 = h4_to_f4(v1.x, v1.y);
        float4 f11 = h4_to_f4(v1.z, v1.w);
        a0.x += f00.x + f10.x; a0.y += f00.y + f10.y;
        a0.z += f00.z + f10.z; a0.w += f00.w + f10.w;
        a1.x += f01.x + f11.x; a1.y += f01.y + f11.y;
        a1.z += f01.z + f11.z; a1.w += f01.w + f11.w;
    }
    // combine the 2 groups
    a0.x += __shfl_xor_sync(0xffffffffu, a0.x, 16);
    a0.y += __shfl_xor_sync(0xffffffffu, a0.y, 16);
    a0.z += __shfl_xor_sync(0xffffffffu, a0.z, 16);
    a0.w += __shfl_xor_sync(0xffffffffu, a0.w, 16);
    a1.x += __shfl_xor_sync(0xffffffffu, a1.x, 16);
    a1.y += __shfl_xor_sync(0xffffffffu, a1.y, 16);
    a1.z += __shfl_xor_sync(0xffffffffu, a1.z, 16);
    a1.w += __shfl_xor_sync(0xffffffffu, a1.w, 16);

    a0.x *= di; a0.y *= di; a0.z *= di; a0.w *= di;
    a1.x *= di; a1.y *= di; a1.z *= di; a1.w *= di;
    float4* out4 = (float4*)g_bufA;
    out4[i * 32 + 2 * sub + grp] = (grp == 0) ? a0 : a1;
}

// h2 = relu(bufA @ W2 + b2) -> bufB.  BM=64, BN=128, BK=16, 256 threads.
// Inner loop in packed fp32x2.
__global__ void k_gemm2(const float* __restrict__ W2, const float* __restrict__ b2) {
    __shared__ float As[16][64];
    __shared__ float Bs[16][128];
    int tid = threadIdx.x;
    int tx = tid & 31;
    int ty = tid >> 5;
    int row0 = blockIdx.x * 64;
    unsigned long long acc2[4][4];
    #pragma unroll
    for (int q = 0; q < 4; q++)
        #pragma unroll
        for (int c = 0; c < 4; c++) acc2[q][c] = 0ull;

    const float* A = g_bufA;
    for (int k0 = 0; k0 < 128; k0 += 16) {
        {
            int r = tid >> 2;
            int kq = (tid & 3) * 4;
            int row = row0 + r;
            float4 v = make_float4(0.f, 0.f, 0.f, 0.f);
            if (row < N_NODES)
                v = ((const float4*)A)[(row * 128 + k0 + kq) >> 2];
            As[kq + 0][r] = v.x;
            As[kq + 1][r] = v.y;
            As[kq + 2][r] = v.z;
            As[kq + 3][r] = v.w;
        }
        {
            const float4* W4 = (const float4*)(W2 + k0 * 128);
            float4* Bs4 = (float4*)&Bs[0][0];
            Bs4[tid] = W4[tid];
            Bs4[tid + 256] = W4[tid + 256];
        }
        __syncthreads();
        #pragma unroll
        for (int k = 0; k < 16; k++) {
            float4 b = *((float4*)&Bs[k][tx * 4]);
            unsigned long long bb[4];
            bb[0] = pack2(b.x, b.x);
            bb[1] = pack2(b.y, b.y);
            bb[2] = pack2(b.z, b.z);
            bb[3] = pack2(b.w, b.w);
            #pragma unroll
            for (int q = 0; q < 4; q++) {
                unsigned long long a2 =
                    *(const unsigned long long*)&As[k][ty * 8 + 2 * q];
                fma2(acc2[q][0], a2, bb[0]);
                fma2(acc2[q][1], a2, bb[1]);
                fma2(acc2[q][2], a2, bb[2]);
                fma2(acc2[q][3], a2, bb[3]);
            }
        }
        __syncthreads();
    }
    float4 bias = ((const float4*)b2)[tx];
    #pragma unroll
    for (int q = 0; q < 4; q++) {
        float lo[4], hi[4];
        #pragma unroll
        for (int c = 0; c < 4; c++) unpack2(acc2[q][c], lo[c], hi[c]);
        int r0 = row0 + ty * 8 + 2 * q;
        if (r0 < N_NODES) {
            float4 v = make_float4(fmaxf(lo[0] + bias.x, 0.f),
                                   fmaxf(lo[1] + bias.y, 0.f),
                                   fmaxf(lo[2] + bias.z, 0.f),
                                   fmaxf(lo[3] + bias.w, 0.f));
            ((float4*)g_bufB)[r0 * 32 + tx] = v;
        }
        if (r0 + 1 < N_NODES) {
            float4 v = make_float4(fmaxf(hi[0] + bias.x, 0.f),
                                   fmaxf(hi[1] + bias.y, 0.f),
                                   fmaxf(hi[2] + bias.z, 0.f),
                                   fmaxf(hi[3] + bias.w, 0.f));
            ((float4*)g_bufB)[(r0 + 1) * 32 + tx] = v;
        }
    }
}

// pool sums from bufB (batch sorted -> local accumulation); also graph counts.
__global__ void k_pool(const void* batch) {
    int tid = threadIdx.x;
    int start = blockIdx.x * 128;
    int end = min(start + 128, N_NODES);
    if (start >= N_NODES) return;
    int is64 = g_is64;
    int curg = ld_idx(batch, start, is64);
    float acc = 0.f;
    int runlen = 0;
    for (int n = start; n < end; n++) {
        int g = ld_idx(batch, n, is64);
        if (g != curg) {
            atomicAdd(&g_pool[curg * 128 + tid], acc);
            if (tid == 0) atomicAdd(&g_gcnt[curg], runlen);
            acc = 0.f; runlen = 0;
            curg = g;
        }
        acc += g_bufB[n * 128 + tid];
        runlen++;
    }
    atomicAdd(&g_pool[curg * 128 + tid], acc);
    if (tid == 0) atomicAdd(&g_gcnt[curg], runlen);
}

__global__ void k_final(const float* __restrict__ Wfc,
                        const float* __restrict__ bfc,
                        float* __restrict__ out) {
    int tid = threadIdx.x;   // 1024 = 64*16
    int g = tid >> 4;
    int o = tid & 15;
    float c = (float)max(g_gcnt[g], 1);
    float s = 0.f;
    #pragma unroll 8
    for (int k = 0; k < 128; k++)
        s = fmaf(g_pool[g * 128 + k], Wfc[k * 16 + o], s);
    out[tid] = s / c + bfc[o];
}

// ---------------- launch ----------------------------------------------------
extern "C" void kernel_launch(void* const* d_in, const int* in_sizes, int n_in,
                              void* d_out, int out_size) {
    const float* x   = (const float*)d_in[0];
    const void*  ei  = d_in[1];
    const void*  bat = d_in[2];
    const float* W1  = (const float*)d_in[3];
    const float* b1  = (const float*)d_in[4];
    const float* W2  = (const float*)d_in[5];
    const float* b2  = (const float*)d_in[6];
    const float* Wfc = (const float*)d_in[7];
    const float* bfc = (const float*)d_in[8];
    float* out = (float*)d_out;

    k_init<<<(N_NODES + 255) / 256, 256>>>();                 // 1
    k_build<<<(N_EDGES + 255) / 256, 256>>>(ei);              // 2
    k_dinvxs<<<(N_NODES * 16 + 255) / 256, 256>>>(x);         // 3
    k_aggx<<<(N_NODES * 32 + 255) / 256, 256>>>();            // 4  <- ncu slot
    k_gemm1<<<(N_NODES + 31) / 32, 128>>>(W1, b1);            // 5
    k_aggh<<<(N_NODES + 7) / 8, 256>>>();                     // 6
    k_gemm2<<<(N_NODES + 63) / 64, 256>>>(W2, b2);            // 7
    k_pool<<<(N_NODES + 127) / 128, 128>>>(bat);              // 8
    k_final<<<1, 1024>>>(Wfc, bfc, out);                      // 9
}